// round 13
// baseline (speedup 1.0000x reference)
#include <cuda_runtime.h>
#include <cuda_bf16.h>
#include <cstdint>

#define T_LEN   2048
#define Dh      64
#define Hh      8
#define Bb      2
#define BHn     16
#define STATE   512
#define NTHREADS 128
#define CHUNK   1024
#define NCHUNK  2

typedef __nv_bfloat16 bf16;

// Pre-split operands (device scratch)
__device__ bf16 g_Kh[(size_t)BHn * T_LEN * Dh];
__device__ bf16 g_Kl[(size_t)BHn * T_LEN * Dh];
__device__ bf16 g_Vth[(size_t)BHn * Dh * T_LEN];   // transposed [bh][d][s]
__device__ bf16 g_Vtl[(size_t)BHn * Dh * T_LEN];
__device__ bf16 g_Wh[(size_t)STATE * STATE];
__device__ bf16 g_Wl[(size_t)STATE * STATE];
// Split-K partials: unnormalized O (bf16 hi/lo) per chunk + row sums
__device__ bf16 g_POh[(size_t)NCHUNK * Bb * T_LEN * STATE];
__device__ bf16 g_POl[(size_t)NCHUNK * Bb * T_LEN * STATE];
__device__ float g_Pl[(size_t)NCHUNK * BHn * T_LEN];
// Normalized attention output, bf16 hi/lo, [B, T, STATE]
__device__ bf16 g_Xh[(size_t)Bb * T_LEN * STATE];
__device__ bf16 g_Xl[(size_t)Bb * T_LEN * STATE];
__device__ int  g_len[Bb];

__device__ __forceinline__ void split2(float x, float y, uint32_t& h, uint32_t& l)
{
    __nv_bfloat162 hh = __floats2bfloat162_rn(x, y);
    float rx = x - __bfloat162float(hh.x);
    float ry = y - __bfloat162float(hh.y);
    __nv_bfloat162 ll = __floats2bfloat162_rn(rx, ry);
    h = *reinterpret_cast<uint32_t*>(&hh);
    l = *reinterpret_cast<uint32_t*>(&ll);
}

__device__ __forceinline__ float ex2(float x)
{
    float y;
    asm("ex2.approx.f32 %0, %1;" : "=f"(y) : "f"(x));
    return y;
}

#define MMA_BF16(c, a, b0, b1)                                                  \
    asm volatile(                                                               \
        "mma.sync.aligned.m16n8k16.row.col.f32.bf16.bf16.f32 "                  \
        "{%0,%1,%2,%3}, {%4,%5,%6,%7}, {%8,%9}, {%0,%1,%2,%3};"                 \
        : "+f"((c)[0]), "+f"((c)[1]), "+f"((c)[2]), "+f"((c)[3])                \
        : "r"((a)[0]), "r"((a)[1]), "r"((a)[2]), "r"((a)[3]),                   \
          "r"(b0), "r"(b1))

#define CP16(smem_u32, gptr)                                                    \
    asm volatile("cp.async.cg.shared.global [%0], [%1], 16;"                    \
                 :: "r"(smem_u32), "l"(gptr))

__device__ __forceinline__ void ldsm4(uint32_t& r0, uint32_t& r1,
                                      uint32_t& r2, uint32_t& r3, uint32_t addr)
{
    asm volatile("ldmatrix.sync.aligned.m8n8.x4.shared.b16 {%0,%1,%2,%3}, [%4];"
                 : "=r"(r0), "=r"(r1), "=r"(r2), "=r"(r3) : "r"(addr));
}

__device__ __forceinline__ uint32_t s2u(const void* p)
{
    return (uint32_t)__cvta_generic_to_shared(p);
}

// Attention smem stage: 4 arrays of [64][72] (Kh,Kl,Vth,Vtl)
#define ARR     (64 * 72)
#define STAGE   (4 * ARR)
#define ROWB    (72 * 2)

// Merge smem stage: Xh,Xl [128][72]; Wh,Wl [64][72]
#define XARR    (128 * 72)
#define WARR    (64 * 72)
#define MSTAGE  (2 * XARR + 2 * WARR)

#define NK2  (BHn * T_LEN * Dh / 2)
#define NW2  (STATE * STATE / 2)
#define KW_BLOCKS ((NK2 + NW2 + 255) / 256)

// ---------------------------------------------------------------------------
// Pre-pass: fused K and W fp32 -> bf16 hi/lo split + per-batch length count
// (the last Bb blocks count zeros of src_length_mask).
// ---------------------------------------------------------------------------
__global__ void split_kw(const float* __restrict__ k, const float* __restrict__ w,
                         const int* __restrict__ lm)
{
    if ((int)blockIdx.x >= KW_BLOCKS) {
        __shared__ int part[8];
        const int b = blockIdx.x - KW_BLOCKS, tid = threadIdx.x;
        int c = 0;
        for (int s = tid; s < T_LEN; s += 256) c += (lm[b * T_LEN + s] == 0);
        c += __shfl_xor_sync(0xffffffffu, c, 1);
        c += __shfl_xor_sync(0xffffffffu, c, 2);
        c += __shfl_xor_sync(0xffffffffu, c, 4);
        c += __shfl_xor_sync(0xffffffffu, c, 8);
        c += __shfl_xor_sync(0xffffffffu, c, 16);
        if ((tid & 31) == 0) part[tid >> 5] = c;
        __syncthreads();
        if (tid == 0) {
            int t = 0;
            for (int i = 0; i < 8; i++) t += part[i];
            g_len[b] = t;
        }
        return;
    }
    const int i = blockIdx.x * blockDim.x + threadIdx.x;
    if (i < NK2) {
        const float2 x = ((const float2*)k)[i];
        uint32_t h, l;
        split2(x.x, x.y, h, l);
        ((uint32_t*)g_Kh)[i] = h;
        ((uint32_t*)g_Kl)[i] = l;
    } else if (i < NK2 + NW2) {
        const int j = i - NK2;
        const float2 x = ((const float2*)w)[j];
        uint32_t h, l;
        split2(x.x, x.y, h, l);
        ((uint32_t*)g_Wh)[j] = h;
        ((uint32_t*)g_Wl)[j] = l;
    }
}

// ---------------------------------------------------------------------------
// Pre-pass: V -> transposed bf16 hi/lo [bh][d][s]
// ---------------------------------------------------------------------------
__global__ void __launch_bounds__(128) prep_v(const float* __restrict__ v)
{
    __shared__ bf16 Th[64][72];
    __shared__ bf16 Tl[64][72];
    const int tid = threadIdx.x;
    const int s0 = blockIdx.x * 64;
    const int bh = blockIdx.y;

    for (int i = tid; i < 64 * 16; i += 128) {
        const int row = i >> 4, c4 = i & 15;
        const float4 x = *(const float4*)(v + ((size_t)bh * T_LEN + s0 + row) * Dh + c4 * 4);
        const float vals[4] = { x.x, x.y, x.z, x.w };
#pragma unroll
        for (int j = 0; j < 4; j++) {
            const bf16 vh = __float2bfloat16(vals[j]);
            Th[c4 * 4 + j][row] = vh;
            Tl[c4 * 4 + j][row] = __float2bfloat16(vals[j] - __bfloat162float(vh));
        }
    }
    __syncthreads();
    for (int i = tid; i < 64 * 8; i += 128) {
        const int d = i >> 3, c = i & 7;
        const size_t base = ((size_t)bh * Dh + d) * T_LEN + s0;
        *(uint4*)(g_Vth + base + c * 8) = *(const uint4*)&Th[d][c * 8];
        *(uint4*)(g_Vtl + base + c * 8) = *(const uint4*)&Tl[d][c * 8];
    }
}

// ---------------------------------------------------------------------------
// cp.async one 64-key tile (Kh,Kl,Vth,Vtl) into a stage.
// ---------------------------------------------------------------------------
__device__ __forceinline__ void load_tile_async(bf16* stage, int bh, int s0, int tid)
{
    const bf16* kh = g_Kh + ((size_t)bh * T_LEN + s0) * Dh;
    const bf16* kl = g_Kl + ((size_t)bh * T_LEN + s0) * Dh;
#pragma unroll
    for (int i = tid; i < 512; i += NTHREADS) {
        const int row = i >> 3, c = (i & 7) * 8;
        const int so = row * 72 + c;
        CP16(s2u(stage + so), kh + row * Dh + c);
        CP16(s2u(stage + ARR + so), kl + row * Dh + c);
        const size_t vb = ((size_t)bh * Dh + row) * T_LEN + s0 + c;
        CP16(s2u(stage + 2 * ARR + so), g_Vth + vb);
        CP16(s2u(stage + 3 * ARR + so), g_Vtl + vb);
    }
}

// ---------------------------------------------------------------------------
// Flash attention, split-K (measured-best R10 shape): grid (32, 2, 16).
// BM=64, 4 warps (warp M=16). Fixed-max softmax => partials additive.
// ---------------------------------------------------------------------------
__global__ void __launch_bounds__(NTHREADS, 3)
attn_kernel(const float* __restrict__ q)
{
    extern __shared__ __align__(16) bf16 smem[];   // 2 * STAGE

    const int tid  = threadIdx.x;
    const int lane = tid & 31;
    const int w    = tid >> 5;
    const int bh   = blockIdx.z;
    const int b    = bh >> 3;
    const int h    = bh & 7;
    const int m0   = (31 - blockIdx.x) * 64;    // long CTAs launch first
    const int chunk = blockIdx.y;
    const int L    = g_len[b];

    const int s_begin = chunk * CHUNK;
    const int key_end = min(m0 + 64, L);
    if (s_begin >= key_end) return;             // inactive chunk CTA

    const int t_begin = s_begin >> 6;
    const int t_end   = min((key_end + 63) >> 6, t_begin + (CHUNK >> 6));
    const int n_clean_g = min(m0 >> 6, L >> 6);

    load_tile_async(smem, bh, t_begin * 64, tid);
    asm volatile("cp.async.commit_group;");

    const int r    = lane >> 2;
    const int qoff = (lane & 3) * 2;
    const int t0   = m0 + w * 16 + r;
    const int t1   = t0 + 8;

    const uint32_t lmB = (uint32_t)(((lane & 7) + ((lane >> 4) << 3)) * ROWB
                                    + ((lane >> 3) & 1) * 16);

    // Q fragments (hi/lo); fold (1/sqrt(d)) * log2(e)
    const float QSC = 0.125f * 1.4426950408889634f;
    uint32_t qa_h[4][4], qa_l[4][4];
    {
        const float* qb = q + ((size_t)bh * T_LEN) * Dh;
#pragma unroll
        for (int ks = 0; ks < 4; ks++) {
            const int c = ks * 16 + qoff;
            const float2 x0 = *(const float2*)(qb + (size_t)t0 * Dh + c);
            const float2 x1 = *(const float2*)(qb + (size_t)t1 * Dh + c);
            const float2 x2 = *(const float2*)(qb + (size_t)t0 * Dh + c + 8);
            const float2 x3 = *(const float2*)(qb + (size_t)t1 * Dh + c + 8);
            split2(x0.x * QSC, x0.y * QSC, qa_h[ks][0], qa_l[ks][0]);
            split2(x1.x * QSC, x1.y * QSC, qa_h[ks][1], qa_l[ks][1]);
            split2(x2.x * QSC, x2.y * QSC, qa_h[ks][2], qa_l[ks][2]);
            split2(x3.x * QSC, x3.y * QSC, qa_h[ks][3], qa_l[ks][3]);
        }
    }

    float l_i0 = 0.f, l_i1 = 0.f;
    float o_c[8][4];
#pragma unroll
    for (int dt = 0; dt < 8; dt++)
#pragma unroll
        for (int e = 0; e < 4; e++) o_c[dt][e] = 0.f;

    const uint32_t usmem = s2u(smem);

    for (int it = t_begin; it < t_end; it++) {
        const int s0 = it * 64;
        const int j  = it - t_begin;

        __syncthreads();
        if (it + 1 < t_end)
            load_tile_async(smem + ((j + 1) & 1) * STAGE, bh, s0 + 64, tid);
        asm volatile("cp.async.commit_group;");
        asm volatile("cp.async.wait_group 1;");
        __syncthreads();

        const uint32_t ub  = usmem + (j & 1) * (STAGE * 2);
        const uint32_t uKh = ub + lmB;
        const uint32_t uKl = uKh + ARR * 2;
        const uint32_t uVh = uKl + ARR * 2;
        const uint32_t uVl = uVh + ARR * 2;

        // ---- S = Q K^T (3-term bf16 split; log2 domain) ----
        float s_c[8][4];
#pragma unroll
        for (int nt = 0; nt < 8; nt++)
#pragma unroll
            for (int e = 0; e < 4; e++) s_c[nt][e] = 0.f;

#pragma unroll
        for (int ks = 0; ks < 4; ks++) {
            const uint32_t co = ks * 32;
#pragma unroll
            for (int np = 0; np < 4; np++) {
                const uint32_t off = np * (16 * ROWB) + co;
                uint32_t h0, h1, h2, h3, l0, l1, l2, l3;
                ldsm4(h0, h1, h2, h3, uKh + off);
                ldsm4(l0, l1, l2, l3, uKl + off);
                MMA_BF16(s_c[2 * np],     qa_h[ks], h0, h1);
                MMA_BF16(s_c[2 * np],     qa_h[ks], l0, l1);
                MMA_BF16(s_c[2 * np],     qa_l[ks], h0, h1);
                MMA_BF16(s_c[2 * np + 1], qa_h[ks], h2, h3);
                MMA_BF16(s_c[2 * np + 1], qa_h[ks], l2, l3);
                MMA_BF16(s_c[2 * np + 1], qa_l[ks], h2, h3);
            }
        }

        // ---- masks only on boundary/diagonal tiles ----
        if (it >= n_clean_g) {
#pragma unroll
            for (int nt = 0; nt < 8; nt++) {
#pragma unroll
                for (int e = 0; e < 2; e++) {
                    const int sg = s0 + nt * 8 + qoff + e;
                    const bool lenm = (sg >= L);
                    if (lenm || sg > t0) s_c[nt][e] = -1e30f;
                    if (lenm || sg > t1) s_c[nt][2 + e] = -1e30f;
                }
            }
        }

        // ---- p = 2^s, accumulate partial sums, pack P frags ----
        uint32_t pa_h[4][4], pa_l[4][4];
#pragma unroll
        for (int g = 0; g < 4; g++) {
            float p00 = ex2(s_c[2 * g][0]),     p01 = ex2(s_c[2 * g][1]);
            float p02 = ex2(s_c[2 * g][2]),     p03 = ex2(s_c[2 * g][3]);
            float p10 = ex2(s_c[2 * g + 1][0]), p11 = ex2(s_c[2 * g + 1][1]);
            float p12 = ex2(s_c[2 * g + 1][2]), p13 = ex2(s_c[2 * g + 1][3]);
            l_i0 += p00 + p01 + p10 + p11;
            l_i1 += p02 + p03 + p12 + p13;
            split2(p00, p01, pa_h[g][0], pa_l[g][0]);
            split2(p02, p03, pa_h[g][1], pa_l[g][1]);
            split2(p10, p11, pa_h[g][2], pa_l[g][2]);
            split2(p12, p13, pa_h[g][3], pa_l[g][3]);
        }

        // ---- O += P V (3-term bf16 split) ----
#pragma unroll
        for (int g = 0; g < 4; g++) {
            const uint32_t co = g * 32;
#pragma unroll
            for (int dp = 0; dp < 4; dp++) {
                const uint32_t off = dp * (16 * ROWB) + co;
                uint32_t h0, h1, h2, h3, l0, l1, l2, l3;
                ldsm4(h0, h1, h2, h3, uVh + off);
                ldsm4(l0, l1, l2, l3, uVl + off);
                MMA_BF16(o_c[2 * dp],     pa_h[g], h0, h1);
                MMA_BF16(o_c[2 * dp],     pa_h[g], l0, l1);
                MMA_BF16(o_c[2 * dp],     pa_l[g], h0, h1);
                MMA_BF16(o_c[2 * dp + 1], pa_h[g], h2, h3);
                MMA_BF16(o_c[2 * dp + 1], pa_h[g], l2, l3);
                MMA_BF16(o_c[2 * dp + 1], pa_l[g], h2, h3);
            }
        }
    }

    // ---- write UNNORMALIZED partial O + partial row sums ----
    l_i0 += __shfl_xor_sync(0xffffffffu, l_i0, 1);
    l_i0 += __shfl_xor_sync(0xffffffffu, l_i0, 2);
    l_i1 += __shfl_xor_sync(0xffffffffu, l_i1, 1);
    l_i1 += __shfl_xor_sync(0xffffffffu, l_i1, 2);
    if ((lane & 3) == 0) {
        g_Pl[(size_t)chunk * BHn * T_LEN + (size_t)bh * T_LEN + t0] = l_i0;
        g_Pl[(size_t)chunk * BHn * T_LEN + (size_t)bh * T_LEN + t1] = l_i1;
    }
    const size_t coff = (size_t)chunk * Bb * T_LEN * STATE;
    const size_t ob0 = coff + ((size_t)(b * T_LEN + t0)) * STATE + h * Dh + qoff;
    const size_t ob1 = coff + ((size_t)(b * T_LEN + t1)) * STATE + h * Dh + qoff;
#pragma unroll
    for (int dt = 0; dt < 8; dt++) {
        uint32_t h0, l0, h1, l1;
        split2(o_c[dt][0], o_c[dt][1], h0, l0);
        split2(o_c[dt][2], o_c[dt][3], h1, l1);
        *(uint32_t*)(g_POh + ob0 + dt * 8) = h0;
        *(uint32_t*)(g_POl + ob0 + dt * 8) = l0;
        *(uint32_t*)(g_POh + ob1 + dt * 8) = h1;
        *(uint32_t*)(g_POl + ob1 + dt * 8) = l1;
    }
}

// ---------------------------------------------------------------------------
// Reduce: sum split-K partials, normalize, emit Xh/Xl. Grid Bb*T, block 128.
// ---------------------------------------------------------------------------
__global__ void __launch_bounds__(128) reduce_kernel()
{
    const int row = blockIdx.x;                 // b*T + t
    const int b = row >> 11;
    const int t = row & (T_LEN - 1);
    const int L = g_len[b];
    const bool two = (t >= CHUNK) && (L > CHUNK);   // matches chunk-1 CTA activity

    const int j  = threadIdx.x * 4;             // 4 elems per thread (512 total)
    const int hh = j >> 6;
    const size_t plbase = (size_t)(b * Hh + hh) * T_LEN + t;
    float l = g_Pl[plbase];
    if (two) l += g_Pl[(size_t)BHn * T_LEN + plbase];
    const float inv = 1.f / l;

    const size_t base = (size_t)row * STATE + j;
    const size_t c1 = (size_t)Bb * T_LEN * STATE;

    float a[4];
    {
        const __nv_bfloat162* ph = (const __nv_bfloat162*)(g_POh + base);
        const __nv_bfloat162* pl = (const __nv_bfloat162*)(g_POl + base);
        a[0] = __bfloat162float(ph[0].x) + __bfloat162float(pl[0].x);
        a[1] = __bfloat162float(ph[0].y) + __bfloat162float(pl[0].y);
        a[2] = __bfloat162float(ph[1].x) + __bfloat162float(pl[1].x);
        a[3] = __bfloat162float(ph[1].y) + __bfloat162float(pl[1].y);
    }
    if (two) {
        const __nv_bfloat162* ph = (const __nv_bfloat162*)(g_POh + c1 + base);
        const __nv_bfloat162* pl = (const __nv_bfloat162*)(g_POl + c1 + base);
        a[0] += __bfloat162float(ph[0].x) + __bfloat162float(pl[0].x);
        a[1] += __bfloat162float(ph[0].y) + __bfloat162float(pl[0].y);
        a[2] += __bfloat162float(ph[1].x) + __bfloat162float(pl[1].x);
        a[3] += __bfloat162float(ph[1].y) + __bfloat162float(pl[1].y);
    }
    uint32_t h0, l0, h1, l1;
    split2(a[0] * inv, a[1] * inv, h0, l0);
    split2(a[2] * inv, a[3] * inv, h1, l1);
    *(uint32_t*)(g_Xh + base)     = h0;
    *(uint32_t*)(g_Xl + base)     = l0;
    *(uint32_t*)(g_Xh + base + 2) = h1;
    *(uint32_t*)(g_Xl + base + 2) = l1;
}

// ---------------------------------------------------------------------------
// cp.async one k-chunk (Xh,Xl rows 0..127; Wh,Wl rows 0..63), 256 threads.
// ---------------------------------------------------------------------------
__device__ __forceinline__ void load_merge_tile(bf16* stage, int m0, int n0,
                                                int k0, int tid)
{
#pragma unroll
    for (int i = tid; i < 1024; i += 256) {
        const int row = i >> 3, c = (i & 7) * 8;
        const int so = row * 72 + c;
        const size_t xb = (size_t)(m0 + row) * STATE + k0 + c;
        CP16(s2u(stage + so), g_Xh + xb);
        CP16(s2u(stage + XARR + so), g_Xl + xb);
    }
#pragma unroll
    for (int i = tid; i < 512; i += 256) {
        const int row = i >> 3, c = (i & 7) * 8;
        const int so = row * 72 + c;
        const size_t wb = (size_t)(n0 + row) * STATE + k0 + c;
        CP16(s2u(stage + 2 * XARR + so), g_Wh + wb);
        CP16(s2u(stage + 2 * XARR + WARR + so), g_Wl + wb);
    }
}

// ---------------------------------------------------------------------------
// Merge GEMM (measured-best R12 shape): M-tile 128, 256 threads = 8 warps,
// warp-M=16, 2-stage cp.async + ldmatrix. Grid (8, 32).
// ---------------------------------------------------------------------------
__global__ void __launch_bounds__(256, 2) merge_kernel(float* __restrict__ out)
{
    extern __shared__ __align__(16) bf16 msmem[];   // 2 * MSTAGE

    const int tid  = threadIdx.x;
    const int lane = tid & 31;
    const int w    = tid >> 5;        // 0..7
    const int n0   = blockIdx.x * 64;
    const int m0   = blockIdx.y * 128;
    const int r    = lane >> 2;
    const int qoff = (lane & 3) * 2;

    const uint32_t lmB = (uint32_t)(((lane & 7) + ((lane >> 4) << 3)) * ROWB
                                    + ((lane >> 3) & 1) * 16);
    const uint32_t lmA = (uint32_t)((w * 16 + (lane & 7) + (((lane >> 3) & 1) << 3)) * ROWB
                                    + ((lane >> 4) << 3) * 2);

    load_merge_tile(msmem, m0, n0, 0, tid);
    asm volatile("cp.async.commit_group;");

    float acc[8][4];
#pragma unroll
    for (int nt = 0; nt < 8; nt++)
#pragma unroll
        for (int e = 0; e < 4; e++) acc[nt][e] = 0.f;

    const uint32_t usmem = s2u(msmem);

    for (int kt = 0; kt < 8; kt++) {
        __syncthreads();
        if (kt + 1 < 8)
            load_merge_tile(msmem + ((kt + 1) & 1) * MSTAGE, m0, n0, (kt + 1) * 64, tid);
        asm volatile("cp.async.commit_group;");
        asm volatile("cp.async.wait_group 1;");
        __syncthreads();

        const uint32_t ub  = usmem + (kt & 1) * (MSTAGE * 2);
        const uint32_t uXh = ub + lmA;
        const uint32_t uXl = uXh + XARR * 2;
        const uint32_t uWh = ub + lmB + 2 * XARR * 2;
        const uint32_t uWl = uWh + WARR * 2;

#pragma unroll
        for (int ks = 0; ks < 4; ks++) {
            const uint32_t co = ks * 32;
            uint32_t a_h[4], a_l[4];
            ldsm4(a_h[0], a_h[1], a_h[2], a_h[3], uXh + co);
            ldsm4(a_l[0], a_l[1], a_l[2], a_l[3], uXl + co);
#pragma unroll
            for (int np = 0; np < 4; np++) {
                const uint32_t off = np * (16 * ROWB) + co;
                uint32_t h0, h1, h2, h3, l0, l1, l2, l3;
                ldsm4(h0, h1, h2, h3, uWh + off);
                ldsm4(l0, l1, l2, l3, uWl + off);
                MMA_BF16(acc[2 * np],     a_h, h0, h1);
                MMA_BF16(acc[2 * np],     a_h, l0, l1);
                MMA_BF16(acc[2 * np],     a_l, h0, h1);
                MMA_BF16(acc[2 * np + 1], a_h, h2, h3);
                MMA_BF16(acc[2 * np + 1], a_h, l2, l3);
                MMA_BF16(acc[2 * np + 1], a_l, h2, h3);
            }
        }
    }

    const int mr0 = m0 + w * 16 + r;
#pragma unroll
    for (int nt = 0; nt < 8; nt++) {
        const int n = n0 + nt * 8 + qoff;
        *(float2*)(out + (size_t)mr0 * STATE + n)       = make_float2(acc[nt][0], acc[nt][1]);
        *(float2*)(out + (size_t)(mr0 + 8) * STATE + n) = make_float2(acc[nt][2], acc[nt][3]);
    }
}

extern "C" void kernel_launch(void* const* d_in, const int* in_sizes, int n_in,
                              void* d_out, int out_size)
{
    const float* q = (const float*)d_in[0];
    const float* k = (const float*)d_in[1];
    const float* v = (const float*)d_in[2];
    const int* lenmask = (const int*)d_in[4];
    const float* W = (const float*)d_in[5];
    float* out = (float*)d_out;

    split_kw<<<KW_BLOCKS + Bb, 256>>>(k, W, lenmask);
    prep_v<<<dim3(T_LEN / 64, BHn), 128>>>(v);

    const int a_smem = 2 * STAGE * (int)sizeof(bf16);    // 73,728 B
    const int m_smem = 2 * MSTAGE * (int)sizeof(bf16);   // 110,592 B
    cudaFuncSetAttribute(attn_kernel, cudaFuncAttributeMaxDynamicSharedMemorySize,
                         a_smem);
    cudaFuncSetAttribute(merge_kernel, cudaFuncAttributeMaxDynamicSharedMemorySize,
                         m_smem);
    attn_kernel<<<dim3(T_LEN / 64, NCHUNK, BHn), NTHREADS, a_smem>>>(q);
    reduce_kernel<<<Bb * T_LEN, 128>>>();
    merge_kernel<<<dim3(STATE / 64, (Bb * T_LEN) / 128), 256, m_smem>>>(out);
}

// round 15
// speedup vs baseline: 1.4386x; 1.4386x over previous
#include <cuda_runtime.h>
#include <cuda_bf16.h>
#include <cstdint>

#define T_LEN   2048
#define Dh      64
#define Hh      8
#define Bb      2
#define BHn     16
#define STATE   512
#define NTHREADS 128
#define CHUNK   1024
#define NCHUNK  2

typedef __nv_bfloat16 bf16;

// Pre-split operands (device scratch)
__device__ bf16 g_Kh[(size_t)BHn * T_LEN * Dh];
__device__ bf16 g_Kl[(size_t)BHn * T_LEN * Dh];
__device__ bf16 g_Vth[(size_t)BHn * Dh * T_LEN];   // transposed [bh][d][s]
__device__ bf16 g_Vtl[(size_t)BHn * Dh * T_LEN];
__device__ bf16 g_Wh[(size_t)STATE * STATE];
__device__ bf16 g_Wl[(size_t)STATE * STATE];
// Split-K partials: unnormalized O (bf16 hi/lo) per chunk + row sums
__device__ bf16 g_POh[(size_t)NCHUNK * Bb * T_LEN * STATE];
__device__ bf16 g_POl[(size_t)NCHUNK * Bb * T_LEN * STATE];
__device__ float g_Pl[(size_t)NCHUNK * BHn * T_LEN];
// Normalized attention output, bf16 hi/lo, [B, T, STATE]
__device__ bf16 g_Xh[(size_t)Bb * T_LEN * STATE];
__device__ bf16 g_Xl[(size_t)Bb * T_LEN * STATE];
__device__ int  g_len[Bb];

__device__ __forceinline__ void split2(float x, float y, uint32_t& h, uint32_t& l)
{
    __nv_bfloat162 hh = __floats2bfloat162_rn(x, y);
    float rx = x - __bfloat162float(hh.x);
    float ry = y - __bfloat162float(hh.y);
    __nv_bfloat162 ll = __floats2bfloat162_rn(rx, ry);
    h = *reinterpret_cast<uint32_t*>(&hh);
    l = *reinterpret_cast<uint32_t*>(&ll);
}

__device__ __forceinline__ float ex2(float x)
{
    float y;
    asm("ex2.approx.f32 %0, %1;" : "=f"(y) : "f"(x));
    return y;
}

#define MMA_BF16(c, a, b0, b1)                                                  \
    asm volatile(                                                               \
        "mma.sync.aligned.m16n8k16.row.col.f32.bf16.bf16.f32 "                  \
        "{%0,%1,%2,%3}, {%4,%5,%6,%7}, {%8,%9}, {%0,%1,%2,%3};"                 \
        : "+f"((c)[0]), "+f"((c)[1]), "+f"((c)[2]), "+f"((c)[3])                \
        : "r"((a)[0]), "r"((a)[1]), "r"((a)[2]), "r"((a)[3]),                   \
          "r"(b0), "r"(b1))

#define CP16(smem_u32, gptr)                                                    \
    asm volatile("cp.async.cg.shared.global [%0], [%1], 16;"                    \
                 :: "r"(smem_u32), "l"(gptr))

__device__ __forceinline__ void ldsm4(uint32_t& r0, uint32_t& r1,
                                      uint32_t& r2, uint32_t& r3, uint32_t addr)
{
    asm volatile("ldmatrix.sync.aligned.m8n8.x4.shared.b16 {%0,%1,%2,%3}, [%4];"
                 : "=r"(r0), "=r"(r1), "=r"(r2), "=r"(r3) : "r"(addr));
}

__device__ __forceinline__ uint32_t s2u(const void* p)
{
    return (uint32_t)__cvta_generic_to_shared(p);
}

// Attention smem stage: 4 arrays of [64][72] (Kh,Kl,Vth,Vtl)
#define ARR     (64 * 72)
#define STAGE   (4 * ARR)
#define ROWB    (72 * 2)

// Merge smem stage: Xh,Xl [128][72]; Wh,Wl [64][72]
#define XARR    (128 * 72)
#define WARR    (64 * 72)
#define MSTAGE  (2 * XARR + 2 * WARR)

#define NK2  (BHn * T_LEN * Dh / 2)
#define NW2  (STATE * STATE / 2)

// ---------------------------------------------------------------------------
// Pre-pass: per-batch valid length (count of zeros). Grid Bb, block 256.
// ---------------------------------------------------------------------------
__global__ void len_kernel(const int* __restrict__ lm)
{
    __shared__ int part[8];
    const int b = blockIdx.x, tid = threadIdx.x;
    int c = 0;
    for (int s = tid; s < T_LEN; s += 256) c += (lm[b * T_LEN + s] == 0);
    c += __shfl_xor_sync(0xffffffffu, c, 1);
    c += __shfl_xor_sync(0xffffffffu, c, 2);
    c += __shfl_xor_sync(0xffffffffu, c, 4);
    c += __shfl_xor_sync(0xffffffffu, c, 8);
    c += __shfl_xor_sync(0xffffffffu, c, 16);
    if ((tid & 31) == 0) part[tid >> 5] = c;
    __syncthreads();
    if (tid == 0) {
        int t = 0;
        for (int i = 0; i < 8; i++) t += part[i];
        g_len[b] = t;
    }
}

// ---------------------------------------------------------------------------
// Pre-pass: fused K and W fp32 -> bf16 hi/lo split
// ---------------------------------------------------------------------------
__global__ void split_kw(const float* __restrict__ k, const float* __restrict__ w)
{
    const int i = blockIdx.x * blockDim.x + threadIdx.x;
    if (i < NK2) {
        const float2 x = ((const float2*)k)[i];
        uint32_t h, l;
        split2(x.x, x.y, h, l);
        ((uint32_t*)g_Kh)[i] = h;
        ((uint32_t*)g_Kl)[i] = l;
    } else if (i < NK2 + NW2) {
        const int j = i - NK2;
        const float2 x = ((const float2*)w)[j];
        uint32_t h, l;
        split2(x.x, x.y, h, l);
        ((uint32_t*)g_Wh)[j] = h;
        ((uint32_t*)g_Wl)[j] = l;
    }
}

// ---------------------------------------------------------------------------
// Pre-pass: V -> transposed bf16 hi/lo [bh][d][s]
// ---------------------------------------------------------------------------
__global__ void __launch_bounds__(128) prep_v(const float* __restrict__ v)
{
    __shared__ bf16 Th[64][72];
    __shared__ bf16 Tl[64][72];
    const int tid = threadIdx.x;
    const int s0 = blockIdx.x * 64;
    const int bh = blockIdx.y;

    for (int i = tid; i < 64 * 16; i += 128) {
        const int row = i >> 4, c4 = i & 15;
        const float4 x = *(const float4*)(v + ((size_t)bh * T_LEN + s0 + row) * Dh + c4 * 4);
        const float vals[4] = { x.x, x.y, x.z, x.w };
#pragma unroll
        for (int j = 0; j < 4; j++) {
            const bf16 vh = __float2bfloat16(vals[j]);
            Th[c4 * 4 + j][row] = vh;
            Tl[c4 * 4 + j][row] = __float2bfloat16(vals[j] - __bfloat162float(vh));
        }
    }
    __syncthreads();
    for (int i = tid; i < 64 * 8; i += 128) {
        const int d = i >> 3, c = i & 7;
        const size_t base = ((size_t)bh * Dh + d) * T_LEN + s0;
        *(uint4*)(g_Vth + base + c * 8) = *(const uint4*)&Th[d][c * 8];
        *(uint4*)(g_Vtl + base + c * 8) = *(const uint4*)&Tl[d][c * 8];
    }
}

// ---------------------------------------------------------------------------
// cp.async one 64-key tile (Kh,Kl,Vth,Vtl) into a stage.
// ---------------------------------------------------------------------------
__device__ __forceinline__ void load_tile_async(bf16* stage, int bh, int s0, int tid)
{
    const bf16* kh = g_Kh + ((size_t)bh * T_LEN + s0) * Dh;
    const bf16* kl = g_Kl + ((size_t)bh * T_LEN + s0) * Dh;
#pragma unroll
    for (int i = tid; i < 512; i += NTHREADS) {
        const int row = i >> 3, c = (i & 7) * 8;
        const int so = row * 72 + c;
        CP16(s2u(stage + so), kh + row * Dh + c);
        CP16(s2u(stage + ARR + so), kl + row * Dh + c);
        const size_t vb = ((size_t)bh * Dh + row) * T_LEN + s0 + c;
        CP16(s2u(stage + 2 * ARR + so), g_Vth + vb);
        CP16(s2u(stage + 3 * ARR + so), g_Vtl + vb);
    }
}

// ---------------------------------------------------------------------------
// Flash attention, split-K (R10 measured-best): grid (32, 2, 16).
// BM=64, 4 warps (warp M=16). Fixed-max softmax => partials additive.
// ---------------------------------------------------------------------------
__global__ void __launch_bounds__(NTHREADS, 3)
attn_kernel(const float* __restrict__ q)
{
    extern __shared__ __align__(16) bf16 smem[];   // 2 * STAGE

    const int tid  = threadIdx.x;
    const int lane = tid & 31;
    const int w    = tid >> 5;
    const int bh   = blockIdx.z;
    const int b    = bh >> 3;
    const int h    = bh & 7;
    const int m0   = (31 - blockIdx.x) * 64;    // long CTAs launch first
    const int chunk = blockIdx.y;
    const int L    = g_len[b];

    const int s_begin = chunk * CHUNK;
    const int key_end = min(m0 + 64, L);
    if (s_begin >= key_end) return;             // inactive chunk CTA

    const int t_begin = s_begin >> 6;
    const int t_end   = min((key_end + 63) >> 6, t_begin + (CHUNK >> 6));
    const int n_clean_g = min(m0 >> 6, L >> 6);

    load_tile_async(smem, bh, t_begin * 64, tid);
    asm volatile("cp.async.commit_group;");

    const int r    = lane >> 2;
    const int qoff = (lane & 3) * 2;
    const int t0   = m0 + w * 16 + r;
    const int t1   = t0 + 8;

    const uint32_t lmB = (uint32_t)(((lane & 7) + ((lane >> 4) << 3)) * ROWB
                                    + ((lane >> 3) & 1) * 16);

    // Q fragments (hi/lo); fold (1/sqrt(d)) * log2(e)
    const float QSC = 0.125f * 1.4426950408889634f;
    uint32_t qa_h[4][4], qa_l[4][4];
    {
        const float* qb = q + ((size_t)bh * T_LEN) * Dh;
#pragma unroll
        for (int ks = 0; ks < 4; ks++) {
            const int c = ks * 16 + qoff;
            const float2 x0 = *(const float2*)(qb + (size_t)t0 * Dh + c);
            const float2 x1 = *(const float2*)(qb + (size_t)t1 * Dh + c);
            const float2 x2 = *(const float2*)(qb + (size_t)t0 * Dh + c + 8);
            const float2 x3 = *(const float2*)(qb + (size_t)t1 * Dh + c + 8);
            split2(x0.x * QSC, x0.y * QSC, qa_h[ks][0], qa_l[ks][0]);
            split2(x1.x * QSC, x1.y * QSC, qa_h[ks][1], qa_l[ks][1]);
            split2(x2.x * QSC, x2.y * QSC, qa_h[ks][2], qa_l[ks][2]);
            split2(x3.x * QSC, x3.y * QSC, qa_h[ks][3], qa_l[ks][3]);
        }
    }

    float l_i0 = 0.f, l_i1 = 0.f;
    float o_c[8][4];
#pragma unroll
    for (int dt = 0; dt < 8; dt++)
#pragma unroll
        for (int e = 0; e < 4; e++) o_c[dt][e] = 0.f;

    const uint32_t usmem = s2u(smem);

    for (int it = t_begin; it < t_end; it++) {
        const int s0 = it * 64;
        const int j  = it - t_begin;

        __syncthreads();
        if (it + 1 < t_end)
            load_tile_async(smem + ((j + 1) & 1) * STAGE, bh, s0 + 64, tid);
        asm volatile("cp.async.commit_group;");
        asm volatile("cp.async.wait_group 1;");
        __syncthreads();

        const uint32_t ub  = usmem + (j & 1) * (STAGE * 2);
        const uint32_t uKh = ub + lmB;
        const uint32_t uKl = uKh + ARR * 2;
        const uint32_t uVh = uKl + ARR * 2;
        const uint32_t uVl = uVh + ARR * 2;

        // ---- S = Q K^T (3-term bf16 split; log2 domain) ----
        float s_c[8][4];
#pragma unroll
        for (int nt = 0; nt < 8; nt++)
#pragma unroll
            for (int e = 0; e < 4; e++) s_c[nt][e] = 0.f;

#pragma unroll
        for (int ks = 0; ks < 4; ks++) {
            const uint32_t co = ks * 32;
#pragma unroll
            for (int np = 0; np < 4; np++) {
                const uint32_t off = np * (16 * ROWB) + co;
                uint32_t h0, h1, h2, h3, l0, l1, l2, l3;
                ldsm4(h0, h1, h2, h3, uKh + off);
                ldsm4(l0, l1, l2, l3, uKl + off);
                MMA_BF16(s_c[2 * np],     qa_h[ks], h0, h1);
                MMA_BF16(s_c[2 * np],     qa_h[ks], l0, l1);
                MMA_BF16(s_c[2 * np],     qa_l[ks], h0, h1);
                MMA_BF16(s_c[2 * np + 1], qa_h[ks], h2, h3);
                MMA_BF16(s_c[2 * np + 1], qa_h[ks], l2, l3);
                MMA_BF16(s_c[2 * np + 1], qa_l[ks], h2, h3);
            }
        }

        // ---- masks only on boundary/diagonal tiles ----
        if (it >= n_clean_g) {
#pragma unroll
            for (int nt = 0; nt < 8; nt++) {
#pragma unroll
                for (int e = 0; e < 2; e++) {
                    const int sg = s0 + nt * 8 + qoff + e;
                    const bool lenm = (sg >= L);
                    if (lenm || sg > t0) s_c[nt][e] = -1e30f;
                    if (lenm || sg > t1) s_c[nt][2 + e] = -1e30f;
                }
            }
        }

        // ---- p = 2^s, accumulate partial sums, pack P frags ----
        uint32_t pa_h[4][4], pa_l[4][4];
#pragma unroll
        for (int g = 0; g < 4; g++) {
            float p00 = ex2(s_c[2 * g][0]),     p01 = ex2(s_c[2 * g][1]);
            float p02 = ex2(s_c[2 * g][2]),     p03 = ex2(s_c[2 * g][3]);
            float p10 = ex2(s_c[2 * g + 1][0]), p11 = ex2(s_c[2 * g + 1][1]);
            float p12 = ex2(s_c[2 * g + 1][2]), p13 = ex2(s_c[2 * g + 1][3]);
            l_i0 += p00 + p01 + p10 + p11;
            l_i1 += p02 + p03 + p12 + p13;
            split2(p00, p01, pa_h[g][0], pa_l[g][0]);
            split2(p02, p03, pa_h[g][1], pa_l[g][1]);
            split2(p10, p11, pa_h[g][2], pa_l[g][2]);
            split2(p12, p13, pa_h[g][3], pa_l[g][3]);
        }

        // ---- O += P V (3-term bf16 split) ----
#pragma unroll
        for (int g = 0; g < 4; g++) {
            const uint32_t co = g * 32;
#pragma unroll
            for (int dp = 0; dp < 4; dp++) {
                const uint32_t off = dp * (16 * ROWB) + co;
                uint32_t h0, h1, h2, h3, l0, l1, l2, l3;
                ldsm4(h0, h1, h2, h3, uVh + off);
                ldsm4(l0, l1, l2, l3, uVl + off);
                MMA_BF16(o_c[2 * dp],     pa_h[g], h0, h1);
                MMA_BF16(o_c[2 * dp],     pa_h[g], l0, l1);
                MMA_BF16(o_c[2 * dp],     pa_l[g], h0, h1);
                MMA_BF16(o_c[2 * dp + 1], pa_h[g], h2, h3);
                MMA_BF16(o_c[2 * dp + 1], pa_h[g], l2, l3);
                MMA_BF16(o_c[2 * dp + 1], pa_l[g], h2, h3);
            }
        }
    }

    // ---- write UNNORMALIZED partial O + partial row sums ----
    l_i0 += __shfl_xor_sync(0xffffffffu, l_i0, 1);
    l_i0 += __shfl_xor_sync(0xffffffffu, l_i0, 2);
    l_i1 += __shfl_xor_sync(0xffffffffu, l_i1, 1);
    l_i1 += __shfl_xor_sync(0xffffffffu, l_i1, 2);
    if ((lane & 3) == 0) {
        g_Pl[(size_t)chunk * BHn * T_LEN + (size_t)bh * T_LEN + t0] = l_i0;
        g_Pl[(size_t)chunk * BHn * T_LEN + (size_t)bh * T_LEN + t1] = l_i1;
    }
    const size_t coff = (size_t)chunk * Bb * T_LEN * STATE;
    const size_t ob0 = coff + ((size_t)(b * T_LEN + t0)) * STATE + h * Dh + qoff;
    const size_t ob1 = coff + ((size_t)(b * T_LEN + t1)) * STATE + h * Dh + qoff;
#pragma unroll
    for (int dt = 0; dt < 8; dt++) {
        uint32_t h0, l0, h1, l1;
        split2(o_c[dt][0], o_c[dt][1], h0, l0);
        split2(o_c[dt][2], o_c[dt][3], h1, l1);
        *(uint32_t*)(g_POh + ob0 + dt * 8) = h0;
        *(uint32_t*)(g_POl + ob0 + dt * 8) = l0;
        *(uint32_t*)(g_POh + ob1 + dt * 8) = h1;
        *(uint32_t*)(g_POl + ob1 + dt * 8) = l1;
    }
}

// ---------------------------------------------------------------------------
// Reduce: sum split-K partials, normalize, emit Xh/Xl. Grid Bb*T, block 128.
// ---------------------------------------------------------------------------
__global__ void __launch_bounds__(128) reduce_kernel()
{
    const int row = blockIdx.x;                 // b*T + t
    const int b = row >> 11;
    const int t = row & (T_LEN - 1);
    const int L = g_len[b];
    const bool two = (t >= CHUNK) && (L > CHUNK);   // matches chunk-1 CTA activity

    const int j  = threadIdx.x * 4;             // 4 elems per thread (512 total)
    const int hh = j >> 6;
    const size_t plbase = (size_t)(b * Hh + hh) * T_LEN + t;
    float l = g_Pl[plbase];
    if (two) l += g_Pl[(size_t)BHn * T_LEN + plbase];
    const float inv = 1.f / l;

    const size_t base = (size_t)row * STATE + j;
    const size_t c1 = (size_t)Bb * T_LEN * STATE;

    float a[4];
    {
        const __nv_bfloat162* ph = (const __nv_bfloat162*)(g_POh + base);
        const __nv_bfloat162* pl = (const __nv_bfloat162*)(g_POl + base);
        a[0] = __bfloat162float(ph[0].x) + __bfloat162float(pl[0].x);
        a[1] = __bfloat162float(ph[0].y) + __bfloat162float(pl[0].y);
        a[2] = __bfloat162float(ph[1].x) + __bfloat162float(pl[1].x);
        a[3] = __bfloat162float(ph[1].y) + __bfloat162float(pl[1].y);
    }
    if (two) {
        const __nv_bfloat162* ph = (const __nv_bfloat162*)(g_POh + c1 + base);
        const __nv_bfloat162* pl = (const __nv_bfloat162*)(g_POl + c1 + base);
        a[0] += __bfloat162float(ph[0].x) + __bfloat162float(pl[0].x);
        a[1] += __bfloat162float(ph[0].y) + __bfloat162float(pl[0].y);
        a[2] += __bfloat162float(ph[1].x) + __bfloat162float(pl[1].x);
        a[3] += __bfloat162float(ph[1].y) + __bfloat162float(pl[1].y);
    }
    uint32_t h0, l0, h1, l1;
    split2(a[0] * inv, a[1] * inv, h0, l0);
    split2(a[2] * inv, a[3] * inv, h1, l1);
    *(uint32_t*)(g_Xh + base)     = h0;
    *(uint32_t*)(g_Xl + base)     = l0;
    *(uint32_t*)(g_Xh + base + 2) = h1;
    *(uint32_t*)(g_Xl + base + 2) = l1;
}

// ---------------------------------------------------------------------------
// cp.async one k-chunk (Xh,Xl rows 0..127; Wh,Wl rows 0..63), 256 threads.
// ---------------------------------------------------------------------------
__device__ __forceinline__ void load_merge_tile(bf16* stage, int m0, int n0,
                                                int k0, int tid)
{
#pragma unroll
    for (int i = tid; i < 1024; i += 256) {
        const int row = i >> 3, c = (i & 7) * 8;
        const int so = row * 72 + c;
        const size_t xb = (size_t)(m0 + row) * STATE + k0 + c;
        CP16(s2u(stage + so), g_Xh + xb);
        CP16(s2u(stage + XARR + so), g_Xl + xb);
    }
#pragma unroll
    for (int i = tid; i < 512; i += 256) {
        const int row = i >> 3, c = (i & 7) * 8;
        const int so = row * 72 + c;
        const size_t wb = (size_t)(n0 + row) * STATE + k0 + c;
        CP16(s2u(stage + 2 * XARR + so), g_Wh + wb);
        CP16(s2u(stage + 2 * XARR + WARR + so), g_Wl + wb);
    }
}

// ---------------------------------------------------------------------------
// Merge GEMM (R12 measured-best): M-tile 128, 256 threads = 8 warps,
// warp-M=16, 2-stage cp.async + ldmatrix. Grid (8, 32).
// ---------------------------------------------------------------------------
__global__ void __launch_bounds__(256, 2) merge_kernel(float* __restrict__ out)
{
    extern __shared__ __align__(16) bf16 msmem[];   // 2 * MSTAGE

    const int tid  = threadIdx.x;
    const int lane = tid & 31;
    const int w    = tid >> 5;        // 0..7
    const int n0   = blockIdx.x * 64;
    const int m0   = blockIdx.y * 128;
    const int r    = lane >> 2;
    const int qoff = (lane & 3) * 2;

    const uint32_t lmB = (uint32_t)(((lane & 7) + ((lane >> 4) << 3)) * ROWB
                                    + ((lane >> 3) & 1) * 16);
    const uint32_t lmA = (uint32_t)((w * 16 + (lane & 7) + (((lane >> 3) & 1) << 3)) * ROWB
                                    + ((lane >> 4) << 3) * 2);

    load_merge_tile(msmem, m0, n0, 0, tid);
    asm volatile("cp.async.commit_group;");

    float acc[8][4];
#pragma unroll
    for (int nt = 0; nt < 8; nt++)
#pragma unroll
        for (int e = 0; e < 4; e++) acc[nt][e] = 0.f;

    const uint32_t usmem = s2u(msmem);

    for (int kt = 0; kt < 8; kt++) {
        __syncthreads();
        if (kt + 1 < 8)
            load_merge_tile(msmem + ((kt + 1) & 1) * MSTAGE, m0, n0, (kt + 1) * 64, tid);
        asm volatile("cp.async.commit_group;");
        asm volatile("cp.async.wait_group 1;");
        __syncthreads();

        const uint32_t ub  = usmem + (kt & 1) * (MSTAGE * 2);
        const uint32_t uXh = ub + lmA;
        const uint32_t uXl = uXh + XARR * 2;
        const uint32_t uWh = ub + lmB + 2 * XARR * 2;
        const uint32_t uWl = uWh + WARR * 2;

#pragma unroll
        for (int ks = 0; ks < 4; ks++) {
            const uint32_t co = ks * 32;
            uint32_t a_h[4], a_l[4];
            ldsm4(a_h[0], a_h[1], a_h[2], a_h[3], uXh + co);
            ldsm4(a_l[0], a_l[1], a_l[2], a_l[3], uXl + co);
#pragma unroll
            for (int np = 0; np < 4; np++) {
                const uint32_t off = np * (16 * ROWB) + co;
                uint32_t h0, h1, h2, h3, l0, l1, l2, l3;
                ldsm4(h0, h1, h2, h3, uWh + off);
                ldsm4(l0, l1, l2, l3, uWl + off);
                MMA_BF16(acc[2 * np],     a_h, h0, h1);
                MMA_BF16(acc[2 * np],     a_h, l0, l1);
                MMA_BF16(acc[2 * np],     a_l, h0, h1);
                MMA_BF16(acc[2 * np + 1], a_h, h2, h3);
                MMA_BF16(acc[2 * np + 1], a_h, l2, l3);
                MMA_BF16(acc[2 * np + 1], a_l, h2, h3);
            }
        }
    }

    const int mr0 = m0 + w * 16 + r;
#pragma unroll
    for (int nt = 0; nt < 8; nt++) {
        const int n = n0 + nt * 8 + qoff;
        *(float2*)(out + (size_t)mr0 * STATE + n)       = make_float2(acc[nt][0], acc[nt][1]);
        *(float2*)(out + (size_t)(mr0 + 8) * STATE + n) = make_float2(acc[nt][2], acc[nt][3]);
    }
}

extern "C" void kernel_launch(void* const* d_in, const int* in_sizes, int n_in,
                              void* d_out, int out_size)
{
    const float* q = (const float*)d_in[0];
    const float* k = (const float*)d_in[1];
    const float* v = (const float*)d_in[2];
    const int* lenmask = (const int*)d_in[4];
    const float* W = (const float*)d_in[5];
    float* out = (float*)d_out;

    len_kernel<<<Bb, 256>>>(lenmask);
    split_kw<<<(NK2 + NW2 + 255) / 256, 256>>>(k, W);
    prep_v<<<dim3(T_LEN / 64, BHn), 128>>>(v);

    const int a_smem = 2 * STAGE * (int)sizeof(bf16);    // 73,728 B
    const int m_smem = 2 * MSTAGE * (int)sizeof(bf16);   // 110,592 B
    cudaFuncSetAttribute(attn_kernel, cudaFuncAttributeMaxDynamicSharedMemorySize,
                         a_smem);
    cudaFuncSetAttribute(merge_kernel, cudaFuncAttributeMaxDynamicSharedMemorySize,
                         m_smem);
    attn_kernel<<<dim3(T_LEN / 64, NCHUNK, BHn), NTHREADS, a_smem>>>(q);
    reduce_kernel<<<Bb * T_LEN, 128>>>();
    merge_kernel<<<dim3(STATE / 64, (Bb * T_LEN) / 128), 256, m_smem>>>(out);
}

// round 16
// speedup vs baseline: 1.5927x; 1.1072x over previous
#include <cuda_runtime.h>
#include <cuda_bf16.h>
#include <cstdint>

#define T_LEN   2048
#define Dh      64
#define Hh      8
#define Bb      2
#define BHn     16
#define STATE   512
#define NTHREADS 128

typedef __nv_bfloat16 bf16;

// Pre-split operands (device scratch)
__device__ bf16 g_Kh[(size_t)BHn * T_LEN * Dh];
__device__ bf16 g_Kl[(size_t)BHn * T_LEN * Dh];
__device__ bf16 g_Vth[(size_t)BHn * Dh * T_LEN];   // transposed [bh][d][s]
__device__ bf16 g_Vtl[(size_t)BHn * Dh * T_LEN];
__device__ bf16 g_Wh[(size_t)STATE * STATE];
__device__ bf16 g_Wl[(size_t)STATE * STATE];
// Normalized attention output, bf16 hi/lo, [B, T, STATE]
__device__ bf16 g_Xh[(size_t)Bb * T_LEN * STATE];
__device__ bf16 g_Xl[(size_t)Bb * T_LEN * STATE];
__device__ int  g_len[Bb];

// Round-to-nearest hi/lo split (used in cold paths / prep)
__device__ __forceinline__ void split2(float x, float y, uint32_t& h, uint32_t& l)
{
    __nv_bfloat162 hh = __floats2bfloat162_rn(x, y);
    float rx = x - __bfloat162float(hh.x);
    float ry = y - __bfloat162float(hh.y);
    __nv_bfloat162 ll = __floats2bfloat162_rn(rx, ry);
    h = *reinterpret_cast<uint32_t*>(&hh);
    l = *reinterpret_cast<uint32_t*>(&ll);
}

// Fast hi/lo split for the hot path: hi = TRUNCATED bf16 (1 PRMT for the pair),
// lo = rn(x - hi) (exact residual, one F2FP pack). x = hi + lo to ~2^-17.
__device__ __forceinline__ void packfast(float x, float y, uint32_t& h, uint32_t& l)
{
    const uint32_t xb = __float_as_uint(x), yb = __float_as_uint(y);
    uint32_t hh;
    asm("prmt.b32 %0, %1, %2, 0x7632;" : "=r"(hh) : "r"(xb), "r"(yb));
    const float xh = __uint_as_float(xb & 0xffff0000u);
    const float yh = __uint_as_float(yb & 0xffff0000u);
    __nv_bfloat162 ll = __floats2bfloat162_rn(x - xh, y - yh);
    h = hh;
    l = *reinterpret_cast<uint32_t*>(&ll);
}

__device__ __forceinline__ float ex2(float x)
{
    float y;
    asm("ex2.approx.f32 %0, %1;" : "=f"(y) : "f"(x));
    return y;
}

#define MMA_BF16(c, a, b0, b1)                                                  \
    asm volatile(                                                               \
        "mma.sync.aligned.m16n8k16.row.col.f32.bf16.bf16.f32 "                  \
        "{%0,%1,%2,%3}, {%4,%5,%6,%7}, {%8,%9}, {%0,%1,%2,%3};"                 \
        : "+f"((c)[0]), "+f"((c)[1]), "+f"((c)[2]), "+f"((c)[3])                \
        : "r"((a)[0]), "r"((a)[1]), "r"((a)[2]), "r"((a)[3]),                   \
          "r"(b0), "r"(b1))

#define CP16(smem_u32, gptr)                                                    \
    asm volatile("cp.async.cg.shared.global [%0], [%1], 16;"                    \
                 :: "r"(smem_u32), "l"(gptr))

__device__ __forceinline__ void ldsm4(uint32_t& r0, uint32_t& r1,
                                      uint32_t& r2, uint32_t& r3, uint32_t addr)
{
    asm volatile("ldmatrix.sync.aligned.m8n8.x4.shared.b16 {%0,%1,%2,%3}, [%4];"
                 : "=r"(r0), "=r"(r1), "=r"(r2), "=r"(r3) : "r"(addr));
}

__device__ __forceinline__ uint32_t s2u(const void* p)
{
    return (uint32_t)__cvta_generic_to_shared(p);
}

// Attention smem stage: 4 arrays of [64][72] (Kh,Kl,Vth,Vtl)
#define ARR     (64 * 72)
#define STAGE   (4 * ARR)
#define ROWB    (72 * 2)

// Merge smem stage: Xh,Xl [128][72]; Wh,Wl [64][72]
#define XARR    (128 * 72)
#define WARR    (64 * 72)
#define MSTAGE  (2 * XARR + 2 * WARR)

#define NK2  (BHn * T_LEN * Dh / 2)
#define NW2  (STATE * STATE / 2)

// ---------------------------------------------------------------------------
// Pre-pass: per-batch valid length (count of zeros). Grid Bb, block 256.
// ---------------------------------------------------------------------------
__global__ void len_kernel(const int* __restrict__ lm)
{
    __shared__ int part[8];
    const int b = blockIdx.x, tid = threadIdx.x;
    int c = 0;
    for (int s = tid; s < T_LEN; s += 256) c += (lm[b * T_LEN + s] == 0);
    c += __shfl_xor_sync(0xffffffffu, c, 1);
    c += __shfl_xor_sync(0xffffffffu, c, 2);
    c += __shfl_xor_sync(0xffffffffu, c, 4);
    c += __shfl_xor_sync(0xffffffffu, c, 8);
    c += __shfl_xor_sync(0xffffffffu, c, 16);
    if ((tid & 31) == 0) part[tid >> 5] = c;
    __syncthreads();
    if (tid == 0) {
        int t = 0;
        for (int i = 0; i < 8; i++) t += part[i];
        g_len[b] = t;
    }
}

// ---------------------------------------------------------------------------
// Pre-pass: fused K and W fp32 -> bf16 hi/lo split
// ---------------------------------------------------------------------------
__global__ void split_kw(const float* __restrict__ k, const float* __restrict__ w)
{
    const int i = blockIdx.x * blockDim.x + threadIdx.x;
    if (i < NK2) {
        const float2 x = ((const float2*)k)[i];
        uint32_t h, l;
        split2(x.x, x.y, h, l);
        ((uint32_t*)g_Kh)[i] = h;
        ((uint32_t*)g_Kl)[i] = l;
    } else if (i < NK2 + NW2) {
        const int j = i - NK2;
        const float2 x = ((const float2*)w)[j];
        uint32_t h, l;
        split2(x.x, x.y, h, l);
        ((uint32_t*)g_Wh)[j] = h;
        ((uint32_t*)g_Wl)[j] = l;
    }
}

// ---------------------------------------------------------------------------
// Pre-pass: V -> transposed bf16 hi/lo [bh][d][s]
// ---------------------------------------------------------------------------
__global__ void __launch_bounds__(128) prep_v(const float* __restrict__ v)
{
    __shared__ bf16 Th[64][72];
    __shared__ bf16 Tl[64][72];
    const int tid = threadIdx.x;
    const int s0 = blockIdx.x * 64;
    const int bh = blockIdx.y;

    for (int i = tid; i < 64 * 16; i += 128) {
        const int row = i >> 4, c4 = i & 15;
        const float4 x = *(const float4*)(v + ((size_t)bh * T_LEN + s0 + row) * Dh + c4 * 4);
        const float vals[4] = { x.x, x.y, x.z, x.w };
#pragma unroll
        for (int j = 0; j < 4; j++) {
            const bf16 vh = __float2bfloat16(vals[j]);
            Th[c4 * 4 + j][row] = vh;
            Tl[c4 * 4 + j][row] = __float2bfloat16(vals[j] - __bfloat162float(vh));
        }
    }
    __syncthreads();
    for (int i = tid; i < 64 * 8; i += 128) {
        const int d = i >> 3, c = i & 7;
        const size_t base = ((size_t)bh * Dh + d) * T_LEN + s0;
        *(uint4*)(g_Vth + base + c * 8) = *(const uint4*)&Th[d][c * 8];
        *(uint4*)(g_Vtl + base + c * 8) = *(const uint4*)&Tl[d][c * 8];
    }
}

// ---------------------------------------------------------------------------
// cp.async one 64-key tile (Kh,Kl,Vth,Vtl) into a stage.
// ---------------------------------------------------------------------------
__device__ __forceinline__ void load_tile_async(bf16* stage, int bh, int s0, int tid)
{
    const bf16* kh = g_Kh + ((size_t)bh * T_LEN + s0) * Dh;
    const bf16* kl = g_Kl + ((size_t)bh * T_LEN + s0) * Dh;
#pragma unroll
    for (int i = tid; i < 512; i += NTHREADS) {
        const int row = i >> 3, c = (i & 7) * 8;
        const int so = row * 72 + c;
        CP16(s2u(stage + so), kh + row * Dh + c);
        CP16(s2u(stage + ARR + so), kl + row * Dh + c);
        const size_t vb = ((size_t)bh * Dh + row) * T_LEN + s0 + c;
        CP16(s2u(stage + 2 * ARR + so), g_Vth + vb);
        CP16(s2u(stage + 3 * ARR + so), g_Vtl + vb);
    }
}

// ---------------------------------------------------------------------------
// Flash attention: monolithic (R8 shape), BM=64, warp-M=16, 3 CTAs/SM,
// fixed-max softmax + fast truncate-hi P packing. Grid (32,16).
// ---------------------------------------------------------------------------
__global__ void __launch_bounds__(NTHREADS, 3)
attn_kernel(const float* __restrict__ q)
{
    extern __shared__ __align__(16) bf16 smem[];   // 2 * STAGE

    const int tid  = threadIdx.x;
    const int lane = tid & 31;
    const int w    = tid >> 5;
    const int bh   = blockIdx.y;
    const int b    = bh >> 3;
    const int h    = bh & 7;
    const int m0   = (31 - blockIdx.x) * 64;    // long CTAs launch first
    const int L    = g_len[b];

    load_tile_async(smem, bh, 0, tid);
    asm volatile("cp.async.commit_group;");

    const int r    = lane >> 2;
    const int qoff = (lane & 3) * 2;
    const int t0   = m0 + w * 16 + r;
    const int t1   = t0 + 8;

    const uint32_t lmB = (uint32_t)(((lane & 7) + ((lane >> 4) << 3)) * ROWB
                                    + ((lane >> 3) & 1) * 16);

    // Q fragments (hi/lo); fold (1/sqrt(d)) * log2(e)
    const float QSC = 0.125f * 1.4426950408889634f;
    uint32_t qa_h[4][4], qa_l[4][4];
    {
        const float* qb = q + ((size_t)bh * T_LEN) * Dh;
#pragma unroll
        for (int ks = 0; ks < 4; ks++) {
            const int c = ks * 16 + qoff;
            const float2 x0 = *(const float2*)(qb + (size_t)t0 * Dh + c);
            const float2 x1 = *(const float2*)(qb + (size_t)t1 * Dh + c);
            const float2 x2 = *(const float2*)(qb + (size_t)t0 * Dh + c + 8);
            const float2 x3 = *(const float2*)(qb + (size_t)t1 * Dh + c + 8);
            split2(x0.x * QSC, x0.y * QSC, qa_h[ks][0], qa_l[ks][0]);
            split2(x1.x * QSC, x1.y * QSC, qa_h[ks][1], qa_l[ks][1]);
            split2(x2.x * QSC, x2.y * QSC, qa_h[ks][2], qa_l[ks][2]);
            split2(x3.x * QSC, x3.y * QSC, qa_h[ks][3], qa_l[ks][3]);
        }
    }

    const int n_tiles = min((m0 >> 6) + 1, (L + 63) >> 6);
    const int n_clean = min(m0 >> 6, L >> 6);

    float l_i0 = 0.f, l_i1 = 0.f;
    float o_c[8][4];
#pragma unroll
    for (int dt = 0; dt < 8; dt++)
#pragma unroll
        for (int e = 0; e < 4; e++) o_c[dt][e] = 0.f;

    const uint32_t usmem = s2u(smem);

    for (int it = 0; it < n_tiles; it++) {
        const int s0 = it * 64;

        __syncthreads();
        if (it + 1 < n_tiles)
            load_tile_async(smem + ((it + 1) & 1) * STAGE, bh, s0 + 64, tid);
        asm volatile("cp.async.commit_group;");
        asm volatile("cp.async.wait_group 1;");
        __syncthreads();

        const uint32_t ub  = usmem + (it & 1) * (STAGE * 2);
        const uint32_t uKh = ub + lmB;
        const uint32_t uKl = uKh + ARR * 2;
        const uint32_t uVh = uKl + ARR * 2;
        const uint32_t uVl = uVh + ARR * 2;

        // ---- S = Q K^T (3-term bf16 split; log2 domain) ----
        float s_c[8][4];
#pragma unroll
        for (int nt = 0; nt < 8; nt++)
#pragma unroll
            for (int e = 0; e < 4; e++) s_c[nt][e] = 0.f;

#pragma unroll
        for (int ks = 0; ks < 4; ks++) {
            const uint32_t co = ks * 32;
#pragma unroll
            for (int np = 0; np < 4; np++) {
                const uint32_t off = np * (16 * ROWB) + co;
                uint32_t h0, h1, h2, h3, l0, l1, l2, l3;
                ldsm4(h0, h1, h2, h3, uKh + off);
                ldsm4(l0, l1, l2, l3, uKl + off);
                MMA_BF16(s_c[2 * np],     qa_h[ks], h0, h1);
                MMA_BF16(s_c[2 * np],     qa_h[ks], l0, l1);
                MMA_BF16(s_c[2 * np],     qa_l[ks], h0, h1);
                MMA_BF16(s_c[2 * np + 1], qa_h[ks], h2, h3);
                MMA_BF16(s_c[2 * np + 1], qa_h[ks], l2, l3);
                MMA_BF16(s_c[2 * np + 1], qa_l[ks], h2, h3);
            }
        }

        // ---- masks only on boundary/diagonal tiles ----
        if (it >= n_clean) {
#pragma unroll
            for (int nt = 0; nt < 8; nt++) {
#pragma unroll
                for (int e = 0; e < 2; e++) {
                    const int sg = s0 + nt * 8 + qoff + e;
                    const bool lenm = (sg >= L);
                    if (lenm || sg > t0) s_c[nt][e] = -1e30f;
                    if (lenm || sg > t1) s_c[nt][2 + e] = -1e30f;
                }
            }
        }

        // ---- p = 2^s, accumulate partial sums, fast-pack P frags ----
        uint32_t pa_h[4][4], pa_l[4][4];
#pragma unroll
        for (int g = 0; g < 4; g++) {
            float p00 = ex2(s_c[2 * g][0]),     p01 = ex2(s_c[2 * g][1]);
            float p02 = ex2(s_c[2 * g][2]),     p03 = ex2(s_c[2 * g][3]);
            float p10 = ex2(s_c[2 * g + 1][0]), p11 = ex2(s_c[2 * g + 1][1]);
            float p12 = ex2(s_c[2 * g + 1][2]), p13 = ex2(s_c[2 * g + 1][3]);
            l_i0 += p00 + p01 + p10 + p11;
            l_i1 += p02 + p03 + p12 + p13;
            packfast(p00, p01, pa_h[g][0], pa_l[g][0]);
            packfast(p02, p03, pa_h[g][1], pa_l[g][1]);
            packfast(p10, p11, pa_h[g][2], pa_l[g][2]);
            packfast(p12, p13, pa_h[g][3], pa_l[g][3]);
        }

        // ---- O += P V (3-term bf16 split) ----
#pragma unroll
        for (int g = 0; g < 4; g++) {
            const uint32_t co = g * 32;
#pragma unroll
            for (int dp = 0; dp < 4; dp++) {
                const uint32_t off = dp * (16 * ROWB) + co;
                uint32_t h0, h1, h2, h3, l0, l1, l2, l3;
                ldsm4(h0, h1, h2, h3, uVh + off);
                ldsm4(l0, l1, l2, l3, uVl + off);
                MMA_BF16(o_c[2 * dp],     pa_h[g], h0, h1);
                MMA_BF16(o_c[2 * dp],     pa_h[g], l0, l1);
                MMA_BF16(o_c[2 * dp],     pa_l[g], h0, h1);
                MMA_BF16(o_c[2 * dp + 1], pa_h[g], h2, h3);
                MMA_BF16(o_c[2 * dp + 1], pa_h[g], l2, l3);
                MMA_BF16(o_c[2 * dp + 1], pa_l[g], h2, h3);
            }
        }
    }

    // ---- final row-sum reduce, normalize, write scratch ----
    l_i0 += __shfl_xor_sync(0xffffffffu, l_i0, 1);
    l_i0 += __shfl_xor_sync(0xffffffffu, l_i0, 2);
    l_i1 += __shfl_xor_sync(0xffffffffu, l_i1, 1);
    l_i1 += __shfl_xor_sync(0xffffffffu, l_i1, 2);
    const float inv0 = 1.f / l_i0, inv1 = 1.f / l_i1;
    const size_t ob0 = ((size_t)(b * T_LEN + t0)) * STATE + h * Dh + qoff;
    const size_t ob1 = ((size_t)(b * T_LEN + t1)) * STATE + h * Dh + qoff;
#pragma unroll
    for (int dt = 0; dt < 8; dt++) {
        uint32_t h0, l0, h1, l1;
        split2(o_c[dt][0] * inv0, o_c[dt][1] * inv0, h0, l0);
        split2(o_c[dt][2] * inv1, o_c[dt][3] * inv1, h1, l1);
        *(uint32_t*)(g_Xh + ob0 + dt * 8) = h0;
        *(uint32_t*)(g_Xl + ob0 + dt * 8) = l0;
        *(uint32_t*)(g_Xh + ob1 + dt * 8) = h1;
        *(uint32_t*)(g_Xl + ob1 + dt * 8) = l1;
    }
}

// ---------------------------------------------------------------------------
// cp.async one k-chunk (Xh,Xl rows 0..127; Wh,Wl rows 0..63), 256 threads.
// ---------------------------------------------------------------------------
__device__ __forceinline__ void load_merge_tile(bf16* stage, int m0, int n0,
                                                int k0, int tid)
{
#pragma unroll
    for (int i = tid; i < 1024; i += 256) {
        const int row = i >> 3, c = (i & 7) * 8;
        const int so = row * 72 + c;
        const size_t xb = (size_t)(m0 + row) * STATE + k0 + c;
        CP16(s2u(stage + so), g_Xh + xb);
        CP16(s2u(stage + XARR + so), g_Xl + xb);
    }
#pragma unroll
    for (int i = tid; i < 512; i += 256) {
        const int row = i >> 3, c = (i & 7) * 8;
        const int so = row * 72 + c;
        const size_t wb = (size_t)(n0 + row) * STATE + k0 + c;
        CP16(s2u(stage + 2 * XARR + so), g_Wh + wb);
        CP16(s2u(stage + 2 * XARR + WARR + so), g_Wl + wb);
    }
}

// ---------------------------------------------------------------------------
// Merge GEMM (R12 measured-best): M-tile 128, 256 threads = 8 warps,
// warp-M=16, 2-stage cp.async + ldmatrix. Grid (8, 32).
// ---------------------------------------------------------------------------
__global__ void __launch_bounds__(256, 2) merge_kernel(float* __restrict__ out)
{
    extern __shared__ __align__(16) bf16 msmem[];   // 2 * MSTAGE

    const int tid  = threadIdx.x;
    const int lane = tid & 31;
    const int w    = tid >> 5;        // 0..7
    const int n0   = blockIdx.x * 64;
    const int m0   = blockIdx.y * 128;
    const int r    = lane >> 2;
    const int qoff = (lane & 3) * 2;

    const uint32_t lmB = (uint32_t)(((lane & 7) + ((lane >> 4) << 3)) * ROWB
                                    + ((lane >> 3) & 1) * 16);
    const uint32_t lmA = (uint32_t)((w * 16 + (lane & 7) + (((lane >> 3) & 1) << 3)) * ROWB
                                    + ((lane >> 4) << 3) * 2);

    load_merge_tile(msmem, m0, n0, 0, tid);
    asm volatile("cp.async.commit_group;");

    float acc[8][4];
#pragma unroll
    for (int nt = 0; nt < 8; nt++)
#pragma unroll
        for (int e = 0; e < 4; e++) acc[nt][e] = 0.f;

    const uint32_t usmem = s2u(msmem);

    for (int kt = 0; kt < 8; kt++) {
        __syncthreads();
        if (kt + 1 < 8)
            load_merge_tile(msmem + ((kt + 1) & 1) * MSTAGE, m0, n0, (kt + 1) * 64, tid);
        asm volatile("cp.async.commit_group;");
        asm volatile("cp.async.wait_group 1;");
        __syncthreads();

        const uint32_t ub  = usmem + (kt & 1) * (MSTAGE * 2);
        const uint32_t uXh = ub + lmA;
        const uint32_t uXl = uXh + XARR * 2;
        const uint32_t uWh = ub + lmB + 2 * XARR * 2;
        const uint32_t uWl = uWh + WARR * 2;

#pragma unroll
        for (int ks = 0; ks < 4; ks++) {
            const uint32_t co = ks * 32;
            uint32_t a_h[4], a_l[4];
            ldsm4(a_h[0], a_h[1], a_h[2], a_h[3], uXh + co);
            ldsm4(a_l[0], a_l[1], a_l[2], a_l[3], uXl + co);
#pragma unroll
            for (int np = 0; np < 4; np++) {
                const uint32_t off = np * (16 * ROWB) + co;
                uint32_t h0, h1, h2, h3, l0, l1, l2, l3;
                ldsm4(h0, h1, h2, h3, uWh + off);
                ldsm4(l0, l1, l2, l3, uWl + off);
                MMA_BF16(acc[2 * np],     a_h, h0, h1);
                MMA_BF16(acc[2 * np],     a_h, l0, l1);
                MMA_BF16(acc[2 * np],     a_l, h0, h1);
                MMA_BF16(acc[2 * np + 1], a_h, h2, h3);
                MMA_BF16(acc[2 * np + 1], a_h, l2, l3);
                MMA_BF16(acc[2 * np + 1], a_l, h2, h3);
            }
        }
    }

    const int mr0 = m0 + w * 16 + r;
#pragma unroll
    for (int nt = 0; nt < 8; nt++) {
        const int n = n0 + nt * 8 + qoff;
        *(float2*)(out + (size_t)mr0 * STATE + n)       = make_float2(acc[nt][0], acc[nt][1]);
        *(float2*)(out + (size_t)(mr0 + 8) * STATE + n) = make_float2(acc[nt][2], acc[nt][3]);
    }
}

extern "C" void kernel_launch(void* const* d_in, const int* in_sizes, int n_in,
                              void* d_out, int out_size)
{
    const float* q = (const float*)d_in[0];
    const float* k = (const float*)d_in[1];
    const float* v = (const float*)d_in[2];
    const int* lenmask = (const int*)d_in[4];
    const float* W = (const float*)d_in[5];
    float* out = (float*)d_out;

    len_kernel<<<Bb, 256>>>(lenmask);
    split_kw<<<(NK2 + NW2 + 255) / 256, 256>>>(k, W);
    prep_v<<<dim3(T_LEN / 64, BHn), 128>>>(v);

    const int a_smem = 2 * STAGE * (int)sizeof(bf16);    // 73,728 B
    const int m_smem = 2 * MSTAGE * (int)sizeof(bf16);   // 110,592 B
    cudaFuncSetAttribute(attn_kernel, cudaFuncAttributeMaxDynamicSharedMemorySize,
                         a_smem);
    cudaFuncSetAttribute(merge_kernel, cudaFuncAttributeMaxDynamicSharedMemorySize,
                         m_smem);
    attn_kernel<<<dim3(T_LEN / 64, BHn), NTHREADS, a_smem>>>(q);
    merge_kernel<<<dim3(STATE / 64, (Bb * T_LEN) / 128), 256, m_smem>>>(out);
}